// round 8
// baseline (speedup 1.0000x reference)
#include <cuda_runtime.h>
#include <math.h>
#include <stdint.h>

#define S_LEN 2048
#define B_SZ  64
#define XDIM  64
#define HDIM  256
#define ODIM  64

// Scratch (alloc-free rule: __device__ globals)
__device__ float g_U[S_LEN * B_SZ * HDIM];   // U[t,b,:] = feat @ Wih^T + bih + bhh
__device__ float g_Hs[S_LEN * B_SZ * HDIM];  // hidden state ENTERING step t (h_0 = 0)

// ------------------------- packed fp32x2 helpers ---------------------------
__device__ __forceinline__ unsigned long long fma2(unsigned long long a,
                                                   unsigned long long b,
                                                   unsigned long long c) {
    unsigned long long d;
    asm("fma.rn.f32x2 %0, %1, %2, %3;" : "=l"(d) : "l"(a), "l"(b), "l"(c));
    return d;
}
__device__ __forceinline__ unsigned long long add2(unsigned long long a,
                                                   unsigned long long b) {
    unsigned long long d;
    asm("add.rn.f32x2 %0, %1, %2;" : "=l"(d) : "l"(a), "l"(b));
    return d;
}
__device__ __forceinline__ float pk_lo(unsigned long long v) {
    return __uint_as_float((unsigned)(v & 0xffffffffull));
}
__device__ __forceinline__ float pk_hi(unsigned long long v) {
    return __uint_as_float((unsigned)(v >> 32));
}
// splat one fp32 into both lanes of a packed f32x2
__device__ __forceinline__ unsigned long long pk2(float v) {
    unsigned long long d;
    unsigned u = __float_as_uint(v);
    asm("mov.b64 %0, {%1, %2};" : "=l"(d) : "r"(u), "r"(u));
    return d;
}

// ---------------------------------------------------------------------------
// Kernel A: feat = tanh(x @ Wx + bx); U = feat @ Wih^T + (bih + bhh)
// ---------------------------------------------------------------------------
__global__ __launch_bounds__(256, 1) void kA(
    const float* __restrict__ x,
    const float* __restrict__ Wx, const float* __restrict__ bx,
    const float* __restrict__ Wih, const float* __restrict__ bih,
    const float* __restrict__ bhh)
{
    extern __shared__ float sm[];
    float* sWx   = sm;                    // [64][128]
    float* sWihT = sWx + 64 * 128;        // [128][260]
    float* sbx   = sWihT + 128 * 260;     // [128]
    float* sbU   = sbx + 128;             // [256]
    float* sx    = sbU + 256;             // [16][64]
    float* sfeat = sx + 16 * 64;          // [16][128]

    const int t = threadIdx.x;

    for (int idx = t; idx < 64 * 128; idx += 256) sWx[idx] = Wx[idx];
    for (int idx = t; idx < 256 * 128; idx += 256) {
        int i = idx >> 7, j = idx & 127;
        sWihT[j * 260 + i] = Wih[idx];
    }
    if (t < 128) sbx[t] = bx[t];
    sbU[t] = bih[t] + bhh[t];
    __syncthreads();

    const int rg = t >> 6;
    const int jj = t & 63;
    const int ii = jj * 4;
    const int ntiles = (S_LEN * B_SZ) / 16;

    for (int tile = blockIdx.x; tile < ntiles; tile += gridDim.x) {
        const int row0 = tile * 16;
        {
            const float4* src = (const float4*)(x + (size_t)row0 * XDIM);
            ((float4*)sx)[t] = src[t];
        }
        __syncthreads();

        // phase 1: feat = tanh(x @ Wx + bx)
        float a0[4], a1[4];
        #pragma unroll
        for (int q = 0; q < 4; q++) { a0[q] = 0.f; a1[q] = 0.f; }
        #pragma unroll 8
        for (int k = 0; k < 64; k++) {
            float w0 = sWx[k * 128 + jj];
            float w1 = sWx[k * 128 + jj + 64];
            #pragma unroll
            for (int q = 0; q < 4; q++) {
                float xv = sx[(rg * 4 + q) * 64 + k];
                a0[q] = fmaf(xv, w0, a0[q]);
                a1[q] = fmaf(xv, w1, a1[q]);
            }
        }
        #pragma unroll
        for (int q = 0; q < 4; q++) {
            sfeat[(rg * 4 + q) * 128 + jj]      = tanhf(a0[q] + sbx[jj]);
            sfeat[(rg * 4 + q) * 128 + jj + 64] = tanhf(a1[q] + sbx[jj + 64]);
        }
        __syncthreads();

        // phase 2: U = feat @ Wih^T + bias   (packed f32x2)
        unsigned long long acc01[4], acc23[4];
        #pragma unroll
        for (int q = 0; q < 4; q++) { acc01[q] = 0ull; acc23[q] = 0ull; }
        #pragma unroll 2
        for (int j4 = 0; j4 < 128; j4 += 4) {
            float f[4][4];
            #pragma unroll
            for (int q = 0; q < 4; q++)
                *(float4*)&f[q][0] = *(const float4*)&sfeat[(rg * 4 + q) * 128 + j4];
            #pragma unroll
            for (int s = 0; s < 4; s++) {
                ulonglong2 w = *(const ulonglong2*)&sWihT[(j4 + s) * 260 + ii];
                #pragma unroll
                for (int q = 0; q < 4; q++) {
                    unsigned long long fs = pk2(f[q][s]);
                    acc01[q] = fma2(fs, w.x, acc01[q]);
                    acc23[q] = fma2(fs, w.y, acc23[q]);
                }
            }
        }
        float4 bU = *(const float4*)&sbU[ii];
        #pragma unroll
        for (int q = 0; q < 4; q++) {
            float4 o;
            o.x = pk_lo(acc01[q]) + bU.x; o.y = pk_hi(acc01[q]) + bU.y;
            o.z = pk_lo(acc23[q]) + bU.z; o.w = pk_hi(acc23[q]) + bU.w;
            *((float4*)&g_U[(size_t)(row0 + rg * 4 + q) * HDIM + ii]) = o;
        }
        __syncthreads();
    }
}

// ---------------------------------------------------------------------------
// Kernel B v8: sequential recurrence, ONE CTA of 512 threads per batch.
// Threads 2j/2j+1 own output j's two K-halves (128 each, 32 ulonglong2 =
// 64 weight regs per thread — ALL Whh in registers, zero weight smem).
// Partial merge: one shfl.xor(1). h-loads: even lanes broadcast one 16B
// line, odd lanes another -> conflict-free 1 wf per LDS.128 -> 256 wf/step
// (vs v7's ~960). Per-SMSP issue ~512 cyc = the hard FFMA2 floor.
// Two-step-ahead g_U prefetch; h double-buffered; ONE __syncthreads/step;
// no clusters, no mbarriers, no DSMEM.
// ---------------------------------------------------------------------------
__global__ __launch_bounds__(512, 1) void kB(
    const float* __restrict__ Whh,
    const float* __restrict__ sigmas)
{
    __shared__ __align__(16) float sh[2][256];   // double-buffered h

    const int tid  = threadIdx.x;
    const int gi   = tid >> 1;            // output index (0..255)
    const int half = tid & 1;             // K-half of Whh row gi
    const int b    = blockIdx.x;          // batch element
    const bool fin = (half == 0);         // finalizer lane of the pair

    // weights: W[gi][128*half + kk], kk in [0,128) -> 32 ulonglong2 (64 regs)
    ulonglong2 wreg[32];
    {
        const ulonglong2* ws =
            (const ulonglong2*)(Whh + (size_t)gi * HDIM + 128 * half);
        #pragma unroll
        for (int i = 0; i < 32; i++) wreg[i] = ws[i];
    }

    const float alpha = 1.0f / (1.0f + expf(-sigmas[gi & 3]));
    const float oma   = 1.0f - alpha;

    if (tid < 256) { sh[0][tid] = 0.f; sh[1][tid] = 0.f; }
    __syncthreads();

    float h_reg = 0.f;                    // finalizer-owned h[gi]
    // two-step-ahead u pipeline (finalizers only)
    float u0 = fin ? g_U[(size_t)b * HDIM + gi] : 0.f;
    float u1 = fin ? g_U[((size_t)B_SZ + b) * HDIM + gi] : 0.f;
    int cur = 0;

    for (int t = 0; t < S_LEN; t++) {
        const float* hc = sh[cur] + 128 * half;

        // partial = sum_kk W[gi][128*half+kk] * h[128*half+kk]
        unsigned long long a0 = 0ull, a1 = 0ull, a2 = 0ull, a3 = 0ull;
        #pragma unroll
        for (int i = 0; i < 32; i += 2) {
            ulonglong2 h0 = *(const ulonglong2*)&hc[i * 4];
            a0 = fma2(wreg[i].x, h0.x, a0);
            a1 = fma2(wreg[i].y, h0.y, a1);
            ulonglong2 h1 = *(const ulonglong2*)&hc[i * 4 + 4];
            a2 = fma2(wreg[i + 1].x, h1.x, a2);
            a3 = fma2(wreg[i + 1].y, h1.y, a3);
        }
        unsigned long long c = add2(add2(a0, a1), add2(a2, a3));
        const float partial = pk_lo(c) + pk_hi(c);
        const float other   = __shfl_xor_sync(0xffffffffu, partial, 1);

        if (fin) {
            const float u = u0;
            u0 = u1;
            if (t + 2 < S_LEN)
                u1 = g_U[((size_t)(t + 2) * B_SZ + b) * HDIM + gi];

            g_Hs[((size_t)t * B_SZ + b) * HDIM + gi] = h_reg;  // state entering t

            const float s  = partial + other + u;
            const float hn = tanhf(s);
            h_reg = oma * h_reg + alpha * hn;

            sh[cur ^ 1][gi] = h_reg;      // publish for step t+1
        }
        cur ^= 1;
        __syncthreads();
    }
}

// ---------------------------------------------------------------------------
// Kernel C: z = tanh(h @ Whx + bhx); y = z @ Wout + bout
// ---------------------------------------------------------------------------
__global__ __launch_bounds__(256, 1) void kC(
    const float* __restrict__ Whx, const float* __restrict__ bhx,
    const float* __restrict__ Wout, const float* __restrict__ bout,
    float* __restrict__ y)
{
    extern __shared__ float sm[];
    float* sWhx  = sm;                   // [256][128]
    float* sWout = sWhx + 256 * 128;     // [128][64]
    float* sbhx  = sWout + 128 * 64;     // [128]
    float* sbout = sbhx + 128;           // [64]
    float* sht   = sbout + 64;           // [16][256]
    float* sz    = sht + 16 * 256;       // [16][128]

    const int t = threadIdx.x;
    for (int idx = t; idx < 256 * 128; idx += 256) sWhx[idx] = Whx[idx];
    for (int idx = t; idx < 128 * 64; idx += 256) sWout[idx] = Wout[idx];
    if (t < 128) sbhx[t] = bhx[t];
    if (t < 64)  sbout[t] = bout[t];
    __syncthreads();

    const int rg  = t >> 5;
    const int jj4 = (t & 31) * 4;
    const int rr  = t >> 4;
    const int oo4 = (t & 15) * 4;
    const int ntiles = (S_LEN * B_SZ) / 16;

    for (int tile = blockIdx.x; tile < ntiles; tile += gridDim.x) {
        const int row0 = tile * 16;
        {
            const float4* src = (const float4*)(g_Hs + (size_t)row0 * HDIM);
            float4* dst = (float4*)sht;
            #pragma unroll
            for (int q = 0; q < 4; q++) dst[q * 256 + t] = src[q * 256 + t];
        }
        __syncthreads();

        // phase 1: z = tanh(h @ Whx + bhx)   (packed f32x2)
        unsigned long long acc01[2], acc23[2];
        acc01[0] = acc01[1] = acc23[0] = acc23[1] = 0ull;
        #pragma unroll 2
        for (int i4 = 0; i4 < 256; i4 += 4) {
            float h[2][4];
            #pragma unroll
            for (int q = 0; q < 2; q++)
                *(float4*)&h[q][0] = *(const float4*)&sht[(rg * 2 + q) * 256 + i4];
            #pragma unroll
            for (int s = 0; s < 4; s++) {
                ulonglong2 w = *(const ulonglong2*)&sWhx[(i4 + s) * 128 + jj4];
                #pragma unroll
                for (int q = 0; q < 2; q++) {
                    unsigned long long hs = pk2(h[q][s]);
                    acc01[q] = fma2(hs, w.x, acc01[q]);
                    acc23[q] = fma2(hs, w.y, acc23[q]);
                }
            }
        }
        float4 bz = *(const float4*)&sbhx[jj4];
        #pragma unroll
        for (int q = 0; q < 2; q++) {
            int rw = rg * 2 + q;
            sz[rw * 128 + jj4 + 0] = tanhf(pk_lo(acc01[q]) + bz.x);
            sz[rw * 128 + jj4 + 1] = tanhf(pk_hi(acc01[q]) + bz.y);
            sz[rw * 128 + jj4 + 2] = tanhf(pk_lo(acc23[q]) + bz.z);
            sz[rw * 128 + jj4 + 3] = tanhf(pk_hi(acc23[q]) + bz.w);
        }
        __syncthreads();

        // phase 2: y = z @ Wout + bout
        float4 o = make_float4(0.f, 0.f, 0.f, 0.f);
        #pragma unroll 4
        for (int j = 0; j < 128; j++) {
            float4 w = *(const float4*)&sWout[j * 64 + oo4];
            float z = sz[rr * 128 + j];
            o.x = fmaf(z, w.x, o.x);
            o.y = fmaf(z, w.y, o.y);
            o.z = fmaf(z, w.z, o.z);
            o.w = fmaf(z, w.w, o.w);
        }
        float4 bo = *(const float4*)&sbout[oo4];
        o.x += bo.x; o.y += bo.y; o.z += bo.z; o.w += bo.w;
        *((float4*)&y[(size_t)(row0 + rr) * ODIM + oo4]) = o;
        __syncthreads();
    }
}

// ---------------------------------------------------------------------------
extern "C" void kernel_launch(void* const* d_in, const int* in_sizes, int n_in,
                              void* d_out, int out_size)
{
    const float* x      = (const float*)d_in[0];
    const float* Wx     = (const float*)d_in[1];
    const float* bx     = (const float*)d_in[2];
    const float* Wih    = (const float*)d_in[3];
    const float* bih    = (const float*)d_in[4];
    const float* Whh    = (const float*)d_in[5];
    const float* bhh    = (const float*)d_in[6];
    const float* Whx    = (const float*)d_in[7];
    const float* bhx    = (const float*)d_in[8];
    const float* Wout   = (const float*)d_in[9];
    const float* bout   = (const float*)d_in[10];
    const float* sigmas = (const float*)d_in[11];
    float* y = (float*)d_out;

    const size_t smA = (size_t)(64*128 + 128*260 + 128 + 256 + 16*64 + 16*128) * 4;
    const size_t smC = (size_t)(256*128 + 128*64 + 128 + 64 + 16*256 + 16*128) * 4;

    cudaFuncSetAttribute(kA, cudaFuncAttributeMaxDynamicSharedMemorySize, (int)smA);
    cudaFuncSetAttribute(kC, cudaFuncAttributeMaxDynamicSharedMemorySize, (int)smC);

    kA<<<148, 256, smA>>>(x, Wx, bx, Wih, bih, bhh);
    kB<<<64, 512>>>(Whh, sigmas);
    kC<<<148, 256, smC>>>(Whx, bhx, Wout, bout, y);
}

// round 9
// speedup vs baseline: 2.1964x; 2.1964x over previous
#include <cuda_runtime.h>
#include <math.h>
#include <stdint.h>

#define S_LEN 2048
#define B_SZ  64
#define XDIM  64
#define HDIM  256
#define ODIM  64

// Scratch (alloc-free rule: __device__ globals)
__device__ float g_U[S_LEN * B_SZ * HDIM];   // U[t,b,:] = feat @ Wih^T + bih + bhh
__device__ float g_Hs[S_LEN * B_SZ * HDIM];  // hidden state ENTERING step t (h_0 = 0)

// ------------------------- packed fp32x2 helpers ---------------------------
__device__ __forceinline__ unsigned long long fma2(unsigned long long a,
                                                   unsigned long long b,
                                                   unsigned long long c) {
    unsigned long long d;
    asm("fma.rn.f32x2 %0, %1, %2, %3;" : "=l"(d) : "l"(a), "l"(b), "l"(c));
    return d;
}
__device__ __forceinline__ unsigned long long add2(unsigned long long a,
                                                   unsigned long long b) {
    unsigned long long d;
    asm("add.rn.f32x2 %0, %1, %2;" : "=l"(d) : "l"(a), "l"(b));
    return d;
}
__device__ __forceinline__ float pk_lo(unsigned long long v) {
    return __uint_as_float((unsigned)(v & 0xffffffffull));
}
__device__ __forceinline__ float pk_hi(unsigned long long v) {
    return __uint_as_float((unsigned)(v >> 32));
}
// splat one fp32 into both lanes of a packed f32x2
__device__ __forceinline__ unsigned long long pk2(float v) {
    unsigned long long d;
    unsigned u = __float_as_uint(v);
    asm("mov.b64 %0, {%1, %2};" : "=l"(d) : "r"(u), "r"(u));
    return d;
}

__device__ __forceinline__ uint32_t smem_u32(const void* p) {
    uint32_t a;
    asm("{ .reg .u64 t; cvta.to.shared.u64 t, %1; cvt.u32.u64 %0, t; }"
        : "=r"(a) : "l"(p));
    return a;
}
__device__ __forceinline__ uint32_t ctarank() {
    uint32_t r;
    asm("mov.u32 %0, %%cluster_ctarank;" : "=r"(r));
    return r;
}
__device__ __forceinline__ void mbar_init(uint32_t addr, uint32_t cnt) {
    asm volatile("mbarrier.init.shared.b64 [%0], %1;" :: "r"(addr), "r"(cnt) : "memory");
}
__device__ __forceinline__ void mbar_expect_tx(uint32_t addr, uint32_t bytes) {
    asm volatile("mbarrier.arrive.expect_tx.shared.b64 _, [%0], %1;"
                 :: "r"(addr), "r"(bytes) : "memory");
}
__device__ __forceinline__ void mbar_wait_cta(uint32_t addr, uint32_t parity) {
    asm volatile(
        "{\n\t.reg .pred P;\n\t"
        "W_%=:\n\t"
        "mbarrier.try_wait.parity.acquire.cta.shared::cta.b64 P, [%0], %1, 0x989680;\n\t"
        "@!P bra W_%=;\n\t}"
        :: "r"(addr), "r"(parity) : "memory");
}
// single bulk DSMEM push: local smem -> peer smem, completes tx on peer mbar
__device__ __forceinline__ void bulk_push_peer(uint32_t dst_local, uint32_t src_local,
                                               uint32_t bytes, uint32_t mbar_local,
                                               uint32_t peer) {
    asm volatile(
        "{\n\t.reg .b32 rd, rb;\n\t"
        "mapa.shared::cluster.u32 rd, %0, %3;\n\t"
        "mapa.shared::cluster.u32 rb, %2, %3;\n\t"
        "cp.async.bulk.shared::cluster.shared::cta.mbarrier::complete_tx::bytes "
        "[rd], [%1], %4, [rb];\n\t}"
        :: "r"(dst_local), "r"(src_local), "r"(mbar_local), "r"(peer), "r"(bytes)
        : "memory");
}
__device__ __forceinline__ void fence_proxy_async_cta() {
    asm volatile("fence.proxy.async.shared::cta;" ::: "memory");
}

// ---------------------------------------------------------------------------
// Kernel A: feat = tanh(x @ Wx + bx); U = feat @ Wih^T + (bih + bhh)
// ---------------------------------------------------------------------------
__global__ __launch_bounds__(256, 1) void kA(
    const float* __restrict__ x,
    const float* __restrict__ Wx, const float* __restrict__ bx,
    const float* __restrict__ Wih, const float* __restrict__ bih,
    const float* __restrict__ bhh)
{
    extern __shared__ float sm[];
    float* sWx   = sm;                    // [64][128]
    float* sWihT = sWx + 64 * 128;        // [128][260]
    float* sbx   = sWihT + 128 * 260;     // [128]
    float* sbU   = sbx + 128;             // [256]
    float* sx    = sbU + 256;             // [16][64]
    float* sfeat = sx + 16 * 64;          // [16][128]

    const int t = threadIdx.x;

    for (int idx = t; idx < 64 * 128; idx += 256) sWx[idx] = Wx[idx];
    for (int idx = t; idx < 256 * 128; idx += 256) {
        int i = idx >> 7, j = idx & 127;
        sWihT[j * 260 + i] = Wih[idx];
    }
    if (t < 128) sbx[t] = bx[t];
    sbU[t] = bih[t] + bhh[t];
    __syncthreads();

    const int rg = t >> 6;
    const int jj = t & 63;
    const int ii = jj * 4;
    const int ntiles = (S_LEN * B_SZ) / 16;

    for (int tile = blockIdx.x; tile < ntiles; tile += gridDim.x) {
        const int row0 = tile * 16;
        {
            const float4* src = (const float4*)(x + (size_t)row0 * XDIM);
            ((float4*)sx)[t] = src[t];
        }
        __syncthreads();

        // phase 1: feat = tanh(x @ Wx + bx)
        float a0[4], a1[4];
        #pragma unroll
        for (int q = 0; q < 4; q++) { a0[q] = 0.f; a1[q] = 0.f; }
        #pragma unroll 8
        for (int k = 0; k < 64; k++) {
            float w0 = sWx[k * 128 + jj];
            float w1 = sWx[k * 128 + jj + 64];
            #pragma unroll
            for (int q = 0; q < 4; q++) {
                float xv = sx[(rg * 4 + q) * 64 + k];
                a0[q] = fmaf(xv, w0, a0[q]);
                a1[q] = fmaf(xv, w1, a1[q]);
            }
        }
        #pragma unroll
        for (int q = 0; q < 4; q++) {
            sfeat[(rg * 4 + q) * 128 + jj]      = tanhf(a0[q] + sbx[jj]);
            sfeat[(rg * 4 + q) * 128 + jj + 64] = tanhf(a1[q] + sbx[jj + 64]);
        }
        __syncthreads();

        // phase 2: U = feat @ Wih^T + bias   (packed f32x2)
        unsigned long long acc01[4], acc23[4];
        #pragma unroll
        for (int q = 0; q < 4; q++) { acc01[q] = 0ull; acc23[q] = 0ull; }
        #pragma unroll 2
        for (int j4 = 0; j4 < 128; j4 += 4) {
            float f[4][4];
            #pragma unroll
            for (int q = 0; q < 4; q++)
                *(float4*)&f[q][0] = *(const float4*)&sfeat[(rg * 4 + q) * 128 + j4];
            #pragma unroll
            for (int s = 0; s < 4; s++) {
                ulonglong2 w = *(const ulonglong2*)&sWihT[(j4 + s) * 260 + ii];
                #pragma unroll
                for (int q = 0; q < 4; q++) {
                    unsigned long long fs = pk2(f[q][s]);
                    acc01[q] = fma2(fs, w.x, acc01[q]);
                    acc23[q] = fma2(fs, w.y, acc23[q]);
                }
            }
        }
        float4 bU = *(const float4*)&sbU[ii];
        #pragma unroll
        for (int q = 0; q < 4; q++) {
            float4 o;
            o.x = pk_lo(acc01[q]) + bU.x; o.y = pk_hi(acc01[q]) + bU.y;
            o.z = pk_lo(acc23[q]) + bU.z; o.w = pk_hi(acc23[q]) + bU.w;
            *((float4*)&g_U[(size_t)(row0 + rg * 4 + q) * HDIM + ii]) = o;
        }
        __syncthreads();
    }
}

// ---------------------------------------------------------------------------
// Kernel B v9: 2-CTA cluster per batch, pair-in-warp output split, 256 thr.
// Thread t: pair p=t>>1 (output gi=128r+p), half=t&1 (K-half, 64 weight regs
// -> no spill at 256 threads). Partial merge: shfl.xor(1). ONE sync/step.
// Cross-CTA publish: after the barrier, ONE thread issues a single 512-byte
// cp.async.bulk (shared::cta -> peer shared::cluster) completing tx on the
// peer's parity mbar — replaces R4/R5's 128 individual 4B st.async packets.
// h double-buffered sh[2][2][132] (pad 132 -> even/odd-lane LDS.128 hit
// disjoint banks). Two-step-ahead g_U prefetch. Safety: peer's buffer-A
// writes at t+1 happen-after my step-t reads (reads -> BAR -> my bulk ->
// peer mbar -> peer compute -> peer bulk); my step-t bulk's smem reads
// complete before my step-t+2 local writes via the pair-shfl chain.
// ---------------------------------------------------------------------------
__global__ __launch_bounds__(256, 1) __cluster_dims__(2, 1, 1)
void kB(const float* __restrict__ Whh, const float* __restrict__ sigmas)
{
    __shared__ __align__(16) float sh[2][2][132];   // [buf][half][idx], padded
    __shared__ __align__(8)  unsigned long long mbar[2];

    const int tid  = threadIdx.x;
    const int p    = tid >> 1;            // pair index = local output index
    const int half = tid & 1;             // K-half this thread covers
    const uint32_t rank = ctarank();
    const uint32_t peer = rank ^ 1u;
    const int r  = (int)rank;
    const int b  = blockIdx.x >> 1;
    const int gi = r * 128 + p;           // global output index of this pair
    const bool fresh = (half == r);       // my K-half is produced locally
    const bool fin   = (half == 0);       // finalizer lane of the pair
    const int waiter = (r == 0) ? 1 : 0;  // one NON-fresh thread re-arms mbar
    const int sender = (r == 0) ? 0 : 1;  // one FRESH thread issues the bulk

    // weights: W[gi][128*half + kk], kk in [0,128) -> 32 ulonglong2 (64 regs)
    ulonglong2 wreg[32];
    {
        const ulonglong2* ws =
            (const ulonglong2*)(Whh + (size_t)gi * HDIM + 128 * half);
        #pragma unroll
        for (int i = 0; i < 32; i++) wreg[i] = ws[i];
    }

    const float alpha = 1.0f / (1.0f + expf(-sigmas[gi & 3]));
    const float oma   = 1.0f - alpha;

    for (int idx = tid; idx < 2 * 2 * 132; idx += 256) ((float*)sh)[idx] = 0.f;
    const uint32_t mb[2] = { smem_u32(&mbar[0]), smem_u32(&mbar[1]) };
    const uint32_t sh_a  = smem_u32(&sh[0][0][0]);
    if (tid == 0) { mbar_init(mb[0], 1); mbar_init(mb[1], 1); }
    __syncthreads();
    if (tid == waiter) {                  // cover sends of steps 0 and 1
        mbar_expect_tx(mb[0], 512);
        mbar_expect_tx(mb[1], 512);
    }
    __syncthreads();
    asm volatile("barrier.cluster.arrive.aligned;" ::: "memory");
    asm volatile("barrier.cluster.wait.aligned;" ::: "memory");

    float h_reg = 0.f;                    // finalizer-owned h[gi]
    // two-step-ahead u pipeline (finalizers only)
    float u0 = fin ? g_U[(size_t)b * HDIM + gi] : 0.f;
    float u1 = fin ? g_U[((size_t)B_SZ + b) * HDIM + gi] : 0.f;

    for (int t = 0; t < S_LEN; t++) {
        // h entering step t lives in buffer (t+1)&1
        const float* hsrc = sh[(t + 1) & 1][half];

        // remote-half threads wait for the peer's step-(t-1) h values
        if (!fresh && t > 0) {
            const int pm = (t - 1) & 1;
            mbar_wait_cta(mb[pm], (uint32_t)(((t - 1) >> 1) & 1));
            if (tid == waiter)            // re-arm for reuse at step t+1
                mbar_expect_tx(mb[pm], 512);
        }

        // partial = sum_kk W[gi][128*half+kk] * h[128*half+kk]
        unsigned long long a0 = 0ull, a1 = 0ull, a2 = 0ull, a3 = 0ull;
        #pragma unroll
        for (int i = 0; i < 32; i += 2) {
            ulonglong2 h0 = *(const ulonglong2*)&hsrc[i * 4];
            a0 = fma2(wreg[i].x, h0.x, a0);
            a1 = fma2(wreg[i].y, h0.y, a1);
            ulonglong2 h1 = *(const ulonglong2*)&hsrc[i * 4 + 4];
            a2 = fma2(wreg[i + 1].x, h1.x, a2);
            a3 = fma2(wreg[i + 1].y, h1.y, a3);
        }
        unsigned long long c = add2(add2(a0, a1), add2(a2, a3));
        const float partial = pk_lo(c) + pk_hi(c);
        const float other   = __shfl_xor_sync(0xffffffffu, partial, 1);

        if (fin) {
            const float u = u0;
            u0 = u1;
            if (t + 2 < S_LEN)
                u1 = g_U[((size_t)(t + 2) * B_SZ + b) * HDIM + gi];

            g_Hs[((size_t)t * B_SZ + b) * HDIM + gi] = h_reg;  // state entering t

            const float s  = partial + other + u;
            const float hn = tanhf(s);
            h_reg = oma * h_reg + alpha * hn;

            sh[t & 1][r][p] = h_reg;      // local publish for step t+1
        }
        __syncthreads();

        // one 512B bulk push of our 128 fresh h values to the peer
        if (tid == sender && t + 1 < S_LEN) {
            const int wb = t & 1;
            const uint32_t off = (uint32_t)(((wb * 2 + r) * 132) * 4);
            fence_proxy_async_cta();
            bulk_push_peer(sh_a + off, sh_a + off, 512, mb[wb], peer);
        }
    }

    asm volatile("barrier.cluster.arrive.aligned;" ::: "memory");
    asm volatile("barrier.cluster.wait.aligned;" ::: "memory");
}

// ---------------------------------------------------------------------------
// Kernel C: z = tanh(h @ Whx + bhx); y = z @ Wout + bout
// ---------------------------------------------------------------------------
__global__ __launch_bounds__(256, 1) void kC(
    const float* __restrict__ Whx, const float* __restrict__ bhx,
    const float* __restrict__ Wout, const float* __restrict__ bout,
    float* __restrict__ y)
{
    extern __shared__ float sm[];
    float* sWhx  = sm;                   // [256][128]
    float* sWout = sWhx + 256 * 128;     // [128][64]
    float* sbhx  = sWout + 128 * 64;     // [128]
    float* sbout = sbhx + 128;           // [64]
    float* sht   = sbout + 64;           // [16][256]
    float* sz    = sht + 16 * 256;       // [16][128]

    const int t = threadIdx.x;
    for (int idx = t; idx < 256 * 128; idx += 256) sWhx[idx] = Whx[idx];
    for (int idx = t; idx < 128 * 64; idx += 256) sWout[idx] = Wout[idx];
    if (t < 128) sbhx[t] = bhx[t];
    if (t < 64)  sbout[t] = bout[t];
    __syncthreads();

    const int rg  = t >> 5;
    const int jj4 = (t & 31) * 4;
    const int rr  = t >> 4;
    const int oo4 = (t & 15) * 4;
    const int ntiles = (S_LEN * B_SZ) / 16;

    for (int tile = blockIdx.x; tile < ntiles; tile += gridDim.x) {
        const int row0 = tile * 16;
        {
            const float4* src = (const float4*)(g_Hs + (size_t)row0 * HDIM);
            float4* dst = (float4*)sht;
            #pragma unroll
            for (int q = 0; q < 4; q++) dst[q * 256 + t] = src[q * 256 + t];
        }
        __syncthreads();

        // phase 1: z = tanh(h @ Whx + bhx)   (packed f32x2)
        unsigned long long acc01[2], acc23[2];
        acc01[0] = acc01[1] = acc23[0] = acc23[1] = 0ull;
        #pragma unroll 2
        for (int i4 = 0; i4 < 256; i4 += 4) {
            float h[2][4];
            #pragma unroll
            for (int q = 0; q < 2; q++)
                *(float4*)&h[q][0] = *(const float4*)&sht[(rg * 2 + q) * 256 + i4];
            #pragma unroll
            for (int s = 0; s < 4; s++) {
                ulonglong2 w = *(const ulonglong2*)&sWhx[(i4 + s) * 128 + jj4];
                #pragma unroll
                for (int q = 0; q < 2; q++) {
                    unsigned long long hs = pk2(h[q][s]);
                    acc01[q] = fma2(hs, w.x, acc01[q]);
                    acc23[q] = fma2(hs, w.y, acc23[q]);
                }
            }
        }
        float4 bz = *(const float4*)&sbhx[jj4];
        #pragma unroll
        for (int q = 0; q < 2; q++) {
            int rw = rg * 2 + q;
            sz[rw * 128 + jj4 + 0] = tanhf(pk_lo(acc01[q]) + bz.x);
            sz[rw * 128 + jj4 + 1] = tanhf(pk_hi(acc01[q]) + bz.y);
            sz[rw * 128 + jj4 + 2] = tanhf(pk_lo(acc23[q]) + bz.z);
            sz[rw * 128 + jj4 + 3] = tanhf(pk_hi(acc23[q]) + bz.w);
        }
        __syncthreads();

        // phase 2: y = z @ Wout + bout
        float4 o = make_float4(0.f, 0.f, 0.f, 0.f);
        #pragma unroll 4
        for (int j = 0; j < 128; j++) {
            float4 w = *(const float4*)&sWout[j * 64 + oo4];
            float z = sz[rr * 128 + j];
            o.x = fmaf(z, w.x, o.x);
            o.y = fmaf(z, w.y, o.y);
            o.z = fmaf(z, w.z, o.z);
            o.w = fmaf(z, w.w, o.w);
        }
        float4 bo = *(const float4*)&sbout[oo4];
        o.x += bo.x; o.y += bo.y; o.z += bo.z; o.w += bo.w;
        *((float4*)&y[(size_t)(row0 + rr) * ODIM + oo4]) = o;
        __syncthreads();
    }
}

// ---------------------------------------------------------------------------
extern "C" void kernel_launch(void* const* d_in, const int* in_sizes, int n_in,
                              void* d_out, int out_size)
{
    const float* x      = (const float*)d_in[0];
    const float* Wx     = (const float*)d_in[1];
    const float* bx     = (const float*)d_in[2];
    const float* Wih    = (const float*)d_in[3];
    const float* bih    = (const float*)d_in[4];
    const float* Whh    = (const float*)d_in[5];
    const float* bhh    = (const float*)d_in[6];
    const float* Whx    = (const float*)d_in[7];
    const float* bhx    = (const float*)d_in[8];
    const float* Wout   = (const float*)d_in[9];
    const float* bout   = (const float*)d_in[10];
    const float* sigmas = (const float*)d_in[11];
    float* y = (float*)d_out;

    const size_t smA = (size_t)(64*128 + 128*260 + 128 + 256 + 16*64 + 16*128) * 4;
    const size_t smC = (size_t)(256*128 + 128*64 + 128 + 64 + 16*256 + 16*128) * 4;

    cudaFuncSetAttribute(kA, cudaFuncAttributeMaxDynamicSharedMemorySize, (int)smA);
    cudaFuncSetAttribute(kC, cudaFuncAttributeMaxDynamicSharedMemorySize, (int)smC);

    kA<<<148, 256, smA>>>(x, Wx, bx, Wih, bih, bhh);
    kB<<<128, 256>>>(Whh, sigmas);
    kC<<<148, 256, smC>>>(Whx, bhx, Wout, bout, y);
}

// round 10
// speedup vs baseline: 2.7214x; 1.2390x over previous
#include <cuda_runtime.h>
#include <math.h>
#include <stdint.h>

#define S_LEN 2048
#define B_SZ  64
#define XDIM  64
#define HDIM  256
#define ODIM  64

// Scratch (alloc-free rule: __device__ globals)
__device__ float g_U[S_LEN * B_SZ * HDIM];   // U[t,b,:] = feat @ Wih^T + bih + bhh
__device__ float g_Hs[S_LEN * B_SZ * HDIM];  // hidden state ENTERING step t (h_0 = 0)

// ------------------------- packed fp32x2 helpers ---------------------------
__device__ __forceinline__ unsigned long long fma2(unsigned long long a,
                                                   unsigned long long b,
                                                   unsigned long long c) {
    unsigned long long d;
    asm("fma.rn.f32x2 %0, %1, %2, %3;" : "=l"(d) : "l"(a), "l"(b), "l"(c));
    return d;
}
__device__ __forceinline__ unsigned long long add2(unsigned long long a,
                                                   unsigned long long b) {
    unsigned long long d;
    asm("add.rn.f32x2 %0, %1, %2;" : "=l"(d) : "l"(a), "l"(b));
    return d;
}
__device__ __forceinline__ float pk_lo(unsigned long long v) {
    return __uint_as_float((unsigned)(v & 0xffffffffull));
}
__device__ __forceinline__ float pk_hi(unsigned long long v) {
    return __uint_as_float((unsigned)(v >> 32));
}
// splat one fp32 into both lanes of a packed f32x2
__device__ __forceinline__ unsigned long long pk2(float v) {
    unsigned long long d;
    unsigned u = __float_as_uint(v);
    asm("mov.b64 %0, {%1, %2};" : "=l"(d) : "r"(u), "r"(u));
    return d;
}

__device__ __forceinline__ uint32_t smem_u32(const void* p) {
    uint32_t a;
    asm("{ .reg .u64 t; cvta.to.shared.u64 t, %1; cvt.u32.u64 %0, t; }"
        : "=r"(a) : "l"(p));
    return a;
}
__device__ __forceinline__ uint32_t ctarank() {
    uint32_t r;
    asm("mov.u32 %0, %%cluster_ctarank;" : "=r"(r));
    return r;
}
// remote async store with mbarrier transaction completion (no fence needed)
__device__ __forceinline__ void st_async_peer_f32(uint32_t daddr, uint32_t mbaddr,
                                                  uint32_t peer, float v) {
    asm volatile(
        "{\n\t.reg .b32 ra, rb;\n\t"
        "mapa.shared::cluster.u32 ra, %0, %2;\n\t"
        "mapa.shared::cluster.u32 rb, %1, %2;\n\t"
        "st.async.shared::cluster.mbarrier::complete_tx::bytes.f32 [ra], %3, [rb];\n\t}"
        :: "r"(daddr), "r"(mbaddr), "r"(peer), "f"(v) : "memory");
}
__device__ __forceinline__ void mbar_init(uint32_t addr, uint32_t cnt) {
    asm volatile("mbarrier.init.shared.b64 [%0], %1;" :: "r"(addr), "r"(cnt) : "memory");
}
__device__ __forceinline__ void mbar_expect_tx(uint32_t addr, uint32_t bytes) {
    asm volatile("mbarrier.arrive.expect_tx.shared.b64 _, [%0], %1;"
                 :: "r"(addr), "r"(bytes) : "memory");
}
__device__ __forceinline__ void mbar_wait_cta(uint32_t addr, uint32_t parity) {
    asm volatile(
        "{\n\t.reg .pred P;\n\t"
        "W_%=:\n\t"
        "mbarrier.try_wait.parity.acquire.cta.shared::cta.b64 P, [%0], %1, 0x989680;\n\t"
        "@!P bra W_%=;\n\t}"
        :: "r"(addr), "r"(parity) : "memory");
}

// ---------------------------------------------------------------------------
// Kernel A v2: feat = tanh(x @ Wx + bx); U = feat @ Wih^T + (bih + bhh)
// 32-row tiles, 8-row register blocking in both phases, packed f32x2
// everywhere. Weight LDS per FLOP halved vs v1 (kA was L1-bound at 69%).
// Per-(row,col) summation order (k/j ascending) identical to v1 -> bit-
// identical g_U.
// ---------------------------------------------------------------------------
__global__ __launch_bounds__(256, 1) void kA(
    const float* __restrict__ x,
    const float* __restrict__ Wx, const float* __restrict__ bx,
    const float* __restrict__ Wih, const float* __restrict__ bih,
    const float* __restrict__ bhh)
{
    extern __shared__ float sm[];
    float* sWx   = sm;                    // [64][128]
    float* sWihT = sWx + 64 * 128;        // [128][260]
    float* sbx   = sWihT + 128 * 260;     // [128]
    float* sbU   = sbx + 128;             // [256]
    float* sx    = sbU + 256;             // [32][64]
    float* sfeat = sx + 32 * 64;          // [32][128]

    const int t = threadIdx.x;

    for (int idx = t; idx < 64 * 128; idx += 256) sWx[idx] = Wx[idx];
    for (int idx = t; idx < 256 * 128; idx += 256) {
        int i = idx >> 7, j = idx & 127;
        sWihT[j * 260 + i] = Wih[idx];
    }
    if (t < 128) sbx[t] = bx[t];
    sbU[t] = bih[t] + bhh[t];
    __syncthreads();

    const int rg = t >> 6;          // 0..3 -> rows rg*8 + q
    const int c2 = t & 63;          // phase1 col pair {2c2, 2c2+1}
    const int ii = c2 * 4;          // phase2: 4 consecutive outputs
    const int ntiles = (S_LEN * B_SZ) / 32;

    for (int tile = blockIdx.x; tile < ntiles; tile += gridDim.x) {
        const int row0 = tile * 32;
        { // load 32x64 x tile (contiguous 8KB = 512 float4)
            const float4* src = (const float4*)(x + (size_t)row0 * XDIM);
            ((float4*)sx)[t]       = src[t];
            ((float4*)sx)[t + 256] = src[t + 256];
        }
        __syncthreads();

        // phase 1: feat = tanh(x @ Wx + bx)   (packed f32x2, 8 rows/thread)
        unsigned long long a[8];
        #pragma unroll
        for (int q = 0; q < 8; q++) a[q] = 0ull;
        #pragma unroll 2
        for (int k4 = 0; k4 < 64; k4 += 4) {
            float xv[8][4];
            #pragma unroll
            for (int q = 0; q < 8; q++)
                *(float4*)&xv[q][0] = *(const float4*)&sx[(rg * 8 + q) * 64 + k4];
            #pragma unroll
            for (int s = 0; s < 4; s++) {
                unsigned long long w =
                    *(const unsigned long long*)&sWx[(k4 + s) * 128 + 2 * c2];
                #pragma unroll
                for (int q = 0; q < 8; q++)
                    a[q] = fma2(pk2(xv[q][s]), w, a[q]);
            }
        }
        {
            const float bx0 = sbx[2 * c2], bx1 = sbx[2 * c2 + 1];
            #pragma unroll
            for (int q = 0; q < 8; q++) {
                const int row = rg * 8 + q;
                sfeat[row * 128 + 2 * c2]     = tanhf(pk_lo(a[q]) + bx0);
                sfeat[row * 128 + 2 * c2 + 1] = tanhf(pk_hi(a[q]) + bx1);
            }
        }
        __syncthreads();

        // phase 2: U = feat @ Wih^T + bias   (packed f32x2, 8 rows/thread)
        unsigned long long acc01[8], acc23[8];
        #pragma unroll
        for (int q = 0; q < 8; q++) { acc01[q] = 0ull; acc23[q] = 0ull; }
        #pragma unroll 2
        for (int j4 = 0; j4 < 128; j4 += 4) {
            float f[8][4];
            #pragma unroll
            for (int q = 0; q < 8; q++)
                *(float4*)&f[q][0] = *(const float4*)&sfeat[(rg * 8 + q) * 128 + j4];
            #pragma unroll
            for (int s = 0; s < 4; s++) {
                ulonglong2 w = *(const ulonglong2*)&sWihT[(j4 + s) * 260 + ii];
                #pragma unroll
                for (int q = 0; q < 8; q++) {
                    unsigned long long fs = pk2(f[q][s]);
                    acc01[q] = fma2(fs, w.x, acc01[q]);
                    acc23[q] = fma2(fs, w.y, acc23[q]);
                }
            }
        }
        float4 bU = *(const float4*)&sbU[ii];
        #pragma unroll
        for (int q = 0; q < 8; q++) {
            float4 o;
            o.x = pk_lo(acc01[q]) + bU.x; o.y = pk_hi(acc01[q]) + bU.y;
            o.z = pk_lo(acc23[q]) + bU.z; o.w = pk_hi(acc23[q]) + bU.w;
            *((float4*)&g_U[(size_t)(row0 + rg * 8 + q) * HDIM + ii]) = o;
        }
        __syncthreads();
    }
}

// ---------------------------------------------------------------------------
// Kernel B v4 (EXACT R4 winner — best measured recurrence, ~1800us):
// 2-CTA cluster per batch, output-split, h double-buffered by step parity.
// Fresh-half warps compute during the mbar wait (separate-warp layout is
// what every later restructure broke).
// ---------------------------------------------------------------------------
__global__ __launch_bounds__(256, 1) __cluster_dims__(2, 1, 1)
void kB(const float* __restrict__ Whh, const float* __restrict__ sigmas)
{
    __shared__ __align__(16) float sh[2][256];  // double-buffered h vector
    __shared__ __align__(16) float spart[128];  // intra-CTA partial exchange
    __shared__ __align__(8)  unsigned long long mbar[2];

    const int tid   = threadIdx.x;
    const int i_loc = tid & 127;
    const int half  = tid >> 7;
    const uint32_t rank = ctarank();
    const uint32_t peer = rank ^ 1u;
    const int r  = (int)rank;
    const int b  = blockIdx.x >> 1;
    const int gi = r * 128 + i_loc;          // output index this thread serves
    const bool fresh     = (half == r);      // my K-half is produced locally
    const bool finalizer = (half == 0);
    const int waiter_leader = (r == 0) ? 128 : 0;   // one mbar-waiting thread

    // weights: W[gi][128*half + kk], kk in [0,128) -> 32 ulonglong2 = 128 regs
    ulonglong2 wreg[32];
    {
        const ulonglong2* ws =
            (const ulonglong2*)(Whh + (size_t)gi * HDIM + 128 * half);
        #pragma unroll
        for (int i = 0; i < 32; i++) wreg[i] = ws[i];
    }

    const float alpha = 1.0f / (1.0f + expf(-sigmas[gi & 3]));
    const float oma   = 1.0f - alpha;

    sh[0][tid] = 0.f;
    sh[1][tid] = 0.f;
    const uint32_t mb[2] = { smem_u32(&mbar[0]), smem_u32(&mbar[1]) };
    const uint32_t sh_a  = smem_u32(&sh[0][0]);
    if (tid == 0) { mbar_init(mb[0], 1); mbar_init(mb[1], 1); }
    __syncthreads();
    if (tid == waiter_leader) {              // cover sends of steps 0 and 1
        mbar_expect_tx(mb[0], 512);
        mbar_expect_tx(mb[1], 512);
    }
    __syncthreads();
    asm volatile("barrier.cluster.arrive.aligned;" ::: "memory");
    asm volatile("barrier.cluster.wait.aligned;" ::: "memory");

    float h_reg  = 0.f;                      // finalizer-owned h[gi]
    float u_next = finalizer ? g_U[(size_t)b * HDIM + gi] : 0.f;

    for (int t = 0; t < S_LEN; t++) {
        // h entering step t lives in buffer (t-1)&1 == (t+1)&1
        const float* hsrc = sh[(t + 1) & 1] + 128 * half;

        // threads on the remote K-half wait for the peer's step-(t-1) h values
        if (!fresh && t > 0) {
            const int pm = (t - 1) & 1;
            mbar_wait_cta(mb[pm], (uint32_t)(((t - 1) >> 1) & 1));
            if (tid == waiter_leader)        // re-arm for use at step t+1
                mbar_expect_tx(mb[pm], 512);
        }

        // partial = sum_kk W[gi][128*half+kk] * h[128*half+kk]
        unsigned long long a0 = 0ull, a1 = 0ull, a2 = 0ull, a3 = 0ull;
        #pragma unroll
        for (int i = 0; i < 32; i += 2) {
            ulonglong2 h0 = *(const ulonglong2*)&hsrc[i * 4];
            a0 = fma2(wreg[i].x, h0.x, a0);
            a1 = fma2(wreg[i].y, h0.y, a1);
            ulonglong2 h1 = *(const ulonglong2*)&hsrc[i * 4 + 4];
            a2 = fma2(wreg[i + 1].x, h1.x, a2);
            a3 = fma2(wreg[i + 1].y, h1.y, a3);
        }
        unsigned long long c = add2(add2(a0, a1), add2(a2, a3));
        const float partial = pk_lo(c) + pk_hi(c);

        if (!finalizer) spart[i_loc] = partial;
        __syncthreads();

        if (finalizer) {
            const float u = u_next;
            if (t + 1 < S_LEN)
                u_next = g_U[((size_t)(t + 1) * B_SZ + b) * HDIM + gi];
            g_Hs[((size_t)t * B_SZ + b) * HDIM + gi] = h_reg;  // state entering t

            const float s  = partial + spart[i_loc] + u;
            const float hn = tanhf(s);
            h_reg = oma * h_reg + alpha * hn;

            const int wb = t & 1;
            sh[wb][gi] = h_reg;                               // local publish
            st_async_peer_f32(sh_a + (uint32_t)((wb * 256 + gi) * 4),
                              mb[wb], peer, h_reg);           // remote publish + tx
        }
        __syncthreads();
    }

    asm volatile("barrier.cluster.arrive.aligned;" ::: "memory");
    asm volatile("barrier.cluster.wait.aligned;" ::: "memory");
}

// ---------------------------------------------------------------------------
// Kernel C v2: z = tanh(h @ Whx + bhx); y = z @ Wout + bout
// 32-row tiles, 4-row (phase1) / 2-row (phase2) register blocking.
// Summation order (i/j ascending) identical to v1 -> bit-identical y.
// ---------------------------------------------------------------------------
__global__ __launch_bounds__(256, 1) void kC(
    const float* __restrict__ Whx, const float* __restrict__ bhx,
    const float* __restrict__ Wout, const float* __restrict__ bout,
    float* __restrict__ y)
{
    extern __shared__ float sm[];
    float* sWhx  = sm;                   // [256][128]
    float* sWout = sWhx + 256 * 128;     // [128][64]
    float* sbhx  = sWout + 128 * 64;     // [128]
    float* sbout = sbhx + 128;           // [64]
    float* sht   = sbout + 64;           // [32][256]
    float* sz    = sht + 32 * 256;       // [32][128]

    const int t = threadIdx.x;
    for (int idx = t; idx < 256 * 128; idx += 256) sWhx[idx] = Whx[idx];
    for (int idx = t; idx < 128 * 64; idx += 256) sWout[idx] = Wout[idx];
    if (t < 128) sbhx[t] = bhx[t];
    if (t < 64)  sbout[t] = bout[t];
    __syncthreads();

    const int rg  = t >> 5;          // 0..7 -> rows rg*4 + q   (phase1)
    const int jj4 = (t & 31) * 4;    // phase1: 4 consecutive z cols
    const int rr  = t >> 4;          // 0..15 -> rows rr*2 + q2 (phase2)
    const int oo4 = (t & 15) * 4;    // phase2: 4 consecutive outputs
    const int ntiles = (S_LEN * B_SZ) / 32;

    for (int tile = blockIdx.x; tile < ntiles; tile += gridDim.x) {
        const int row0 = tile * 32;
        { // load 32x256 hidden-state tile (contiguous 32KB = 2048 float4)
            const float4* src = (const float4*)(g_Hs + (size_t)row0 * HDIM);
            float4* dst = (float4*)sht;
            #pragma unroll
            for (int q = 0; q < 8; q++) dst[q * 256 + t] = src[q * 256 + t];
        }
        __syncthreads();

        // phase 1: z = tanh(h @ Whx + bhx)   (packed f32x2, 4 rows/thread)
        unsigned long long acc01[4], acc23[4];
        #pragma unroll
        for (int q = 0; q < 4; q++) { acc01[q] = 0ull; acc23[q] = 0ull; }
        #pragma unroll 2
        for (int i4 = 0; i4 < 256; i4 += 4) {
            float hq[4][4];
            #pragma unroll
            for (int q = 0; q < 4; q++)
                *(float4*)&hq[q][0] = *(const float4*)&sht[(rg * 4 + q) * 256 + i4];
            #pragma unroll
            for (int s = 0; s < 4; s++) {
                ulonglong2 w = *(const ulonglong2*)&sWhx[(i4 + s) * 128 + jj4];
                #pragma unroll
                for (int q = 0; q < 4; q++) {
                    unsigned long long hs = pk2(hq[q][s]);
                    acc01[q] = fma2(hs, w.x, acc01[q]);
                    acc23[q] = fma2(hs, w.y, acc23[q]);
                }
            }
        }
        float4 bz = *(const float4*)&sbhx[jj4];
        #pragma unroll
        for (int q = 0; q < 4; q++) {
            const int rw = rg * 4 + q;
            sz[rw * 128 + jj4 + 0] = tanhf(pk_lo(acc01[q]) + bz.x);
            sz[rw * 128 + jj4 + 1] = tanhf(pk_hi(acc01[q]) + bz.y);
            sz[rw * 128 + jj4 + 2] = tanhf(pk_lo(acc23[q]) + bz.z);
            sz[rw * 128 + jj4 + 3] = tanhf(pk_hi(acc23[q]) + bz.w);
        }
        __syncthreads();

        // phase 2: y = z @ Wout + bout   (2 rows/thread)
        float4 o[2];
        o[0] = make_float4(0.f, 0.f, 0.f, 0.f);
        o[1] = make_float4(0.f, 0.f, 0.f, 0.f);
        #pragma unroll 2
        for (int j4 = 0; j4 < 128; j4 += 4) {
            float zq[2][4];
            #pragma unroll
            for (int q2 = 0; q2 < 2; q2++)
                *(float4*)&zq[q2][0] = *(const float4*)&sz[(rr * 2 + q2) * 128 + j4];
            #pragma unroll
            for (int s = 0; s < 4; s++) {
                float4 w = *(const float4*)&sWout[(j4 + s) * 64 + oo4];
                #pragma unroll
                for (int q2 = 0; q2 < 2; q2++) {
                    o[q2].x = fmaf(zq[q2][s], w.x, o[q2].x);
                    o[q2].y = fmaf(zq[q2][s], w.y, o[q2].y);
                    o[q2].z = fmaf(zq[q2][s], w.z, o[q2].z);
                    o[q2].w = fmaf(zq[q2][s], w.w, o[q2].w);
                }
            }
        }
        float4 bo = *(const float4*)&sbout[oo4];
        #pragma unroll
        for (int q2 = 0; q2 < 2; q2++) {
            float4 ov;
            ov.x = o[q2].x + bo.x; ov.y = o[q2].y + bo.y;
            ov.z = o[q2].z + bo.z; ov.w = o[q2].w + bo.w;
            *((float4*)&y[(size_t)(row0 + rr * 2 + q2) * ODIM + oo4]) = ov;
        }
        __syncthreads();
    }
}

// ---------------------------------------------------------------------------
extern "C" void kernel_launch(void* const* d_in, const int* in_sizes, int n_in,
                              void* d_out, int out_size)
{
    const float* x      = (const float*)d_in[0];
    const float* Wx     = (const float*)d_in[1];
    const float* bx     = (const float*)d_in[2];
    const float* Wih    = (const float*)d_in[3];
    const float* bih    = (const float*)d_in[4];
    const float* Whh    = (const float*)d_in[5];
    const float* bhh    = (const float*)d_in[6];
    const float* Whx    = (const float*)d_in[7];
    const float* bhx    = (const float*)d_in[8];
    const float* Wout   = (const float*)d_in[9];
    const float* bout   = (const float*)d_in[10];
    const float* sigmas = (const float*)d_in[11];
    float* y = (float*)d_out;

    const size_t smA = (size_t)(64*128 + 128*260 + 128 + 256 + 32*64 + 32*128) * 4;
    const size_t smC = (size_t)(256*128 + 128*64 + 128 + 64 + 32*256 + 32*128) * 4;

    cudaFuncSetAttribute(kA, cudaFuncAttributeMaxDynamicSharedMemorySize, (int)smA);
    cudaFuncSetAttribute(kC, cudaFuncAttributeMaxDynamicSharedMemorySize, (int)smC);

    kA<<<148, 256, smA>>>(x, Wx, bx, Wih, bih, bhh);
    kB<<<128, 256>>>(Whh, sigmas);
    kC<<<148, 256, smC>>>(Whx, bhx, Wout, bout, y);
}